// round 15
// baseline (speedup 1.0000x reference)
#include <cuda_runtime.h>
#include <math.h>

#define NRES 768
#define DN   256
#define DE   128
#define EF   30
#define NT   24            // residue tiles (768/32)
#define TS   32            // tile size
#define NSUB 16            // sub-iterations per full task (2 i-rows each)
#define NOFF 276           // strict upper-triangular pairs (It < Jt)
#define NBLK (2 * NOFF + NT)   // 576 equal-work blocks
#define RS   40            // sA row stride in words (conflict-free for uint2 frags)

// ---- output layout (floats), concatenation of the reference tuple ----
#define NODE_OFF 0ULL
#define EDGE_OFF (768ULL * 256ULL)                       // 196608
#define IDX_OFF  (EDGE_OFF + 768ULL * 768ULL * 128ULL)   // 75694080
#define MI_OFF   (IDX_OFF + 768ULL * 768ULL)             // 76283904
#define MIJ_OFF  (MI_OFF + 768ULL)                       // 76284672

// scratch: per-residue frames R (row-major 3x3)
__device__ float g_R[NRES * 9];

__device__ __forceinline__ float3 ld3(const float* p) { return make_float3(p[0], p[1], p[2]); }
__device__ __forceinline__ float3 vsub(float3 a, float3 b) { return make_float3(a.x - b.x, a.y - b.y, a.z - b.z); }
__device__ __forceinline__ float  vdot(float3 a, float3 b) { return a.x * b.x + a.y * b.y + a.z * b.z; }
__device__ __forceinline__ float3 vcross(float3 a, float3 b) {
    return make_float3(a.y * b.z - a.z * b.y, a.z * b.x - a.x * b.z, a.x * b.y - a.y * b.x);
}
__device__ __forceinline__ float  vnorm(float3 a) { return sqrtf(vdot(a, a) + 1e-8f); }
__device__ __forceinline__ float3 vunit(float3 a) { float r = 1.0f / vnorm(a); return make_float3(a.x * r, a.y * r, a.z * r); }

// tf32 round (rna) -> fp32 bit pattern with low mantissa cleared
__device__ __forceinline__ unsigned tf32r(float x) {
    unsigned r; asm("cvt.rna.tf32.f32 %0, %1;" : "=r"(r) : "f"(x)); return r;
}

// m16n8k8 tf32 MMA, D += A*B
__device__ __forceinline__ void mma_tf32(float d[4], const unsigned a[4], const unsigned b[2]) {
    asm volatile(
        "mma.sync.aligned.m16n8k8.row.col.f32.tf32.tf32.f32 "
        "{%0,%1,%2,%3}, {%4,%5,%6,%7}, {%8,%9}, {%0,%1,%2,%3};"
        : "+f"(d[0]), "+f"(d[1]), "+f"(d[2]), "+f"(d[3])
        : "r"(a[0]), "r"(a[1]), "r"(a[2]), "r"(a[3]), "r"(b[0]), "r"(b[1]));
}

// map MMA tile row e (0..127) of a sub to global (iG, jG)
__device__ __forceinline__ void rowmap(int e, int ItTS, int JtTS, int sub,
                                       int& iG, int& jG) {
    int f = e & 63;
    int il = f >> 5, jl = f & 31;
    if (e < 64) { iG = ItTS + sub * 2 + il; jG = JtTS + jl; }
    else        { iG = JtTS + jl;           jG = ItTS + sub * 2 + il; }
}

// ============================================================================
// Node kernel (tiny)
// ============================================================================
__global__ void __launch_bounds__(256) node_kernel(
    const float* __restrict__ X, const int* __restrict__ C,
    const float* __restrict__ aux, const float* __restrict__ Wn,
    const float* __restrict__ bn, float* __restrict__ out)
{
    __shared__ float sfeat[7];
    __shared__ float smask;
    const int n = blockIdx.x;

    if (threadIdx.x == 0) {
        const float* xp = X + n * 12;
        float3 Na = ld3(xp), Ca = ld3(xp + 3), Cc = ld3(xp + 6), Ox = ld3(xp + 9);

        float d1 = logf(vnorm(vsub(Ca, Na)) + 0.001f);
        float d2 = logf(vnorm(vsub(Cc, Ca)) + 0.001f);
        float d3 = logf(vnorm(vsub(Ox, Cc)) + 0.001f);
        float a1 = vdot(vunit(vsub(Na, Ca)), vunit(vsub(Cc, Ca)));
        float a2 = vdot(vunit(vsub(Ca, Cc)), vunit(vsub(Ox, Cc)));

        float3 b0 = vsub(Ca, Na), b1 = vsub(Cc, Ca), b2 = vsub(Ox, Cc);
        float3 n1 = vcross(b0, b1), n2 = vcross(b1, b2);
        float3 ub1 = vunit(b1);
        float3 m1 = vcross(n1, ub1);
        float xx = vdot(n1, n2), yy = vdot(m1, n2);
        float r = sqrtf(xx * xx + yy * yy + 1e-8f);

        sfeat[0] = d1; sfeat[1] = d2; sfeat[2] = d3;
        sfeat[3] = a1; sfeat[4] = a2;
        sfeat[5] = yy / r; sfeat[6] = xx / r;

        float mi = (C[n] > 0) ? 1.0f : 0.0f;
        smask = mi;
        out[MI_OFF + n] = mi;

        float3 e1 = ub1;
        float3 v  = vunit(vsub(Na, Ca));
        float d  = vdot(v, e1);
        float3 w = make_float3(v.x - d * e1.x, v.y - d * e1.y, v.z - d * e1.z);
        float3 e2 = vunit(w);
        float3 e3 = vcross(e1, e2);
        float* rp = g_R + n * 9;
        rp[0] = e1.x; rp[1] = e1.y; rp[2] = e1.z;
        rp[3] = e2.x; rp[4] = e2.y; rp[5] = e2.z;
        rp[6] = e3.x; rp[7] = e3.y; rp[8] = e3.z;
    }
    __syncthreads();

    const int c = threadIdx.x;
    float acc = bn[c];
#pragma unroll
    for (int k = 0; k < 7; k++) acc = fmaf(sfeat[k], Wn[k * DN + c], acc);
    float mi = smask;
    out[NODE_OFF + (size_t)n * DN + c] = mi * (acc + aux[(size_t)n * DN + c]);
}

// A smem layout (fragment-native, tf32 hi only): row stride RS=40 words.
__device__ __forceinline__ void astore(unsigned* sA, int e, int k, float v) {
    int idx = e * RS + (((k >> 3) << 2) + (k & 3)) * 2 + (((k & 7) >= 4) ? 1 : 0);
    sA[idx] = tf32r(v);
}

// ============================================================================
// Edge kernel: 576 equal-work blocks (off-diag pairs split in half; diagonal
// tiles whole), 3 blocks/SM (80-reg cap) -> 24 warps/SM streaming width.
// 1xTF32 MMA (weights in registers), fragment-native A tile, epilogue loads
// split around the MMA chain.
// ============================================================================
__global__ void __launch_bounds__(256, 3) edge_kernel(
    const float* __restrict__ X, const int* __restrict__ C,
    const float* __restrict__ aux, const float* __restrict__ We,
    const float* __restrict__ be, float* __restrict__ out)
{
    __shared__ __align__(16) unsigned sA[128 * RS];   // 20 KB: 128 feature rows
    __shared__ float sXi[TS * 12], sXj[TS * 12];
    __shared__ float sRi[TS * 9],  sRj[TS * 9];
    __shared__ int   sCi[TS], sCj[TS];
    __shared__ float sb[DE];

    const int tid = threadIdx.x;
    const int lane = tid & 31, warp = tid >> 5;
    const int gid = lane >> 2, tg = lane & 3;
    const int wm = warp & 1;       // 2 m-blocks of 16 rows
    const int wn = warp >> 1;      // 4 n-blocks of 32 channels
    const int c0 = wn * 32 + tg * 8;

    // ---- block -> (It, Jt, sub range) ----
    int It, Jt, subLo, subHi;
    bool isDiag;
    if (blockIdx.x < 2 * NOFF) {
        // off-diagonal pair, split into two halves of 8 subs
        int pairIdx = blockIdx.x >> 1;
        int half = blockIdx.x & 1;
        int rem = pairIdx, it = 0, len = NT - 1;
        while (rem >= len) { rem -= len; it++; len--; }
        It = it; Jt = it + 1 + rem;
        isDiag = false;
        subLo = half * (NSUB / 2); subHi = subLo + (NSUB / 2);
    } else {
        It = Jt = blockIdx.x - 2 * NOFF;
        isDiag = true;
        subLo = 0; subHi = NSUB;
    }
    const int ItTS = It * TS, JtTS = Jt * TS;

    // ---- B fragments (tf32 hi only) into registers ----
    unsigned Bh[4][4][2];
    {
        const int chan_base = wn * 32 + (gid >> 1) * 8 + (gid & 1);
#pragma unroll
        for (int kt = 0; kt < 4; kt++)
#pragma unroll
            for (int n = 0; n < 4; n++)
#pragma unroll
                for (int s = 0; s < 2; s++) {
                    int k = kt * 8 + tg + s * 4;
                    float w = (k < EF) ? We[k * DE + chan_base + n * 2] : 0.0f;
                    Bh[kt][n][s] = tf32r(w);
                }
    }

    // ---- stage tile data ----
    for (int t = tid; t < TS * 12; t += 256) {
        sXi[t] = X[ItTS * 12 + t];
        sXj[t] = X[JtTS * 12 + t];
    }
    for (int t = tid; t < TS * 9; t += 256) {
        sRi[t] = g_R[ItTS * 9 + t];
        sRj[t] = g_R[JtTS * 9 + t];
    }
    if (tid < TS) { sCi[tid] = C[ItTS + tid]; sCj[tid] = C[JtTS + tid]; }
    if (tid < DE) sb[tid] = be[tid];
    if (tid < 128) {  // zero pad words for k=30,31 (idx 29, 31; never rewritten)
        sA[tid * RS + 29] = 0u;
        sA[tid * RS + 31] = 0u;
    }
    __syncthreads();

    for (int sub = subLo; sub < subHi; sub++) {
        // ---- phase 1: 64 pairs (2 i-rows x 32 j), 4 threads/pair ----
        {
            const int p = tid >> 2, r = tid & 3;
            const int il = p >> 5, jl = p & 31;
            const int iL = sub * 2 + il;
            const int iG = ItTS + iL, jG = JtTS + jl;
            const int frow = il * 32 + jl, rrow = 64 + frow;

            // D: thread handles i-atom r vs all 4 j-atoms (shared both dirs)
            const float xpx = sXi[iL * 12 + r * 3 + 0];
            const float xpy = sXi[iL * 12 + r * 3 + 1];
            const float xpz = sXi[iL * 12 + r * 3 + 2];
#pragma unroll
            for (int q = 0; q < 4; q++) {
                float dx = xpx - sXj[jl * 12 + q * 3 + 0];
                float dy = xpy - sXj[jl * 12 + q * 3 + 1];
                float dz = xpz - sXj[jl * 12 + q * 3 + 2];
                float d2 = dx * dx + dy * dy + dz * dz + 1e-8f;
                float dist = d2 * rsqrtf(d2);
                float v = __logf(dist + 0.01f);
                astore(sA, frow, r * 4 + q, v);
                if (!isDiag) astore(sA, rrow, q * 4 + r, v);
            }

            if (r < 3) {
                // Rrel row r (rev = transpose, no recompute)
                const float a0 = sRi[iL * 9 + r * 3 + 0];
                const float a1 = sRi[iL * 9 + r * 3 + 1];
                const float a2 = sRi[iL * 9 + r * 3 + 2];
#pragma unroll
                for (int q = 0; q < 3; q++) {
                    float v = a0 * sRj[jl * 9 + q * 3 + 0]
                            + a1 * sRj[jl * 9 + q * 3 + 1]
                            + a2 * sRj[jl * 9 + q * 3 + 2];
                    astore(sA, frow, 16 + r * 3 + q, v);
                    if (!isDiag) astore(sA, rrow, 16 + q * 3 + r, v);
                }
            } else {
                // trel (shared norm: ||R dt|| = ||dt||), chain, sep, masks
                float dtx = sXj[jl * 12 + 3] - sXi[iL * 12 + 3];
                float dty = sXj[jl * 12 + 4] - sXi[iL * 12 + 4];
                float dtz = sXj[jl * 12 + 5] - sXi[iL * 12 + 5];
                float rn = rsqrtf(dtx * dtx + dty * dty + dtz * dtz + 1e-8f);
#pragma unroll
                for (int q = 0; q < 3; q++) {
                    float tf = (sRi[iL * 9 + q * 3 + 0] * dtx
                              + sRi[iL * 9 + q * 3 + 1] * dty
                              + sRi[iL * 9 + q * 3 + 2] * dtz) * rn;
                    astore(sA, frow, 25 + q, tf);
                    if (!isDiag) {
                        float tr = -(sRj[jl * 9 + q * 3 + 0] * dtx
                                   + sRj[jl * 9 + q * 3 + 1] * dty
                                   + sRj[jl * 9 + q * 3 + 2] * dtz) * rn;
                        astore(sA, rrow, 25 + q, tr);
                    }
                }
                int ci = sCi[iL], cj = sCj[jl];
                float sc = (ci == cj) ? 1.0f : 0.0f;
                astore(sA, frow, 28, sc);
                int dsep = jG - iG; dsep = min(32, max(-32, dsep));
                float sepv = (float)dsep * (1.0f / 32.0f);
                astore(sA, frow, 29, sepv);
                float mij = (ci > 0 && cj > 0) ? 1.0f : 0.0f;
                out[IDX_OFF + (size_t)iG * NRES + jG] = (float)jG;
                out[MIJ_OFF + (size_t)iG * NRES + jG] = mij;
                if (!isDiag) {
                    astore(sA, rrow, 28, sc);
                    astore(sA, rrow, 29, -sepv);
                    out[IDX_OFF + (size_t)jG * NRES + iG] = (float)iG;
                    out[MIJ_OFF + (size_t)jG * NRES + iG] = mij;
                }
            }
        }
        __syncthreads();

        // ---- phase 2: MMA + epilogue over row-groups of 32 ----
        const int ngroups = isDiag ? 2 : 4;
        for (int g = 0; g < ngroups; g++) {
            const int e0 = g * 32 + wm * 16 + gid;      // row 0
            const int el1 = e0 + 8;                     // row 1

            // analytic row -> (iG, jG, mij)
            int iG0, jG0, iG1, jG1;
            float mj0, mj1;
            {
                int f0 = e0 & 63, f1 = el1 & 63;
                int il0 = f0 >> 5, jl0 = f0 & 31;
                int il1 = f1 >> 5, jl1 = f1 & 31;
                mj0 = (sCi[sub * 2 + il0] > 0 && sCj[jl0] > 0) ? 1.0f : 0.0f;
                mj1 = (sCi[sub * 2 + il1] > 0 && sCj[jl1] > 0) ? 1.0f : 0.0f;
                rowmap(e0, ItTS, JtTS, sub, iG0, jG0);
                rowmap(el1, ItTS, JtTS, sub, iG1, jG1);
            }
            size_t base0 = ((size_t)iG0 * NRES + jG0) * DE + c0;
            size_t base1 = ((size_t)iG1 * NRES + jG1) * DE + c0;

            // row-0 aux hoisted before the MMA chain (8 regs)
            float4 x0 = __ldcs((const float4*)&aux[base0]);
            float4 x1 = __ldcs((const float4*)&aux[base0 + 4]);

            float acc[4][4] = {};
#pragma unroll
            for (int kt = 0; kt < 4; kt++) {
                const unsigned* p0 = &sA[e0 * RS + (kt * 4 + tg) * 2];
                uint2 q0 = *(const uint2*)p0;             // row e0:  ah_k, ah_k+4
                uint2 q1 = *(const uint2*)(p0 + 8 * RS);  // row e0+8
                unsigned ah[4] = {q0.x, q1.x, q0.y, q1.y};
#pragma unroll
                for (int n = 0; n < 4; n++)
                    mma_tf32(acc[n], ah, Bh[kt][n]);
            }

            // row-1 aux issues here, hidden under row-0's epilogue
            float4 y0 = __ldcs((const float4*)&aux[base1]);
            float4 y1 = __ldcs((const float4*)&aux[base1 + 4]);

            float4 bv0 = *(const float4*)&sb[c0];
            float4 bv1 = *(const float4*)&sb[c0 + 4];
            float4 o;
            o.x = mj0 * (acc[0][0] + bv0.x + x0.x);
            o.y = mj0 * (acc[0][1] + bv0.y + x0.y);
            o.z = mj0 * (acc[1][0] + bv0.z + x0.z);
            o.w = mj0 * (acc[1][1] + bv0.w + x0.w);
            __stcs((float4*)&out[EDGE_OFF + base0], o);
            o.x = mj0 * (acc[2][0] + bv1.x + x1.x);
            o.y = mj0 * (acc[2][1] + bv1.y + x1.y);
            o.z = mj0 * (acc[3][0] + bv1.z + x1.z);
            o.w = mj0 * (acc[3][1] + bv1.w + x1.w);
            __stcs((float4*)&out[EDGE_OFF + base0 + 4], o);
            o.x = mj1 * (acc[0][2] + bv0.x + y0.x);
            o.y = mj1 * (acc[0][3] + bv0.y + y0.y);
            o.z = mj1 * (acc[1][2] + bv0.z + y0.z);
            o.w = mj1 * (acc[1][3] + bv0.w + y0.w);
            __stcs((float4*)&out[EDGE_OFF + base1], o);
            o.x = mj1 * (acc[2][2] + bv1.x + y1.x);
            o.y = mj1 * (acc[2][3] + bv1.y + y1.y);
            o.z = mj1 * (acc[3][2] + bv1.z + y1.z);
            o.w = mj1 * (acc[3][3] + bv1.w + y1.w);
            __stcs((float4*)&out[EDGE_OFF + base1 + 4], o);
        }
        __syncthreads();   // protect sA before next sub's phase 1
    }
}

extern "C" void kernel_launch(void* const* d_in, const int* in_sizes, int n_in,
                              void* d_out, int out_size)
{
    const float* X        = (const float*)d_in[0];
    const int*   C        = (const int*)  d_in[1];
    const float* node_aux = (const float*)d_in[2];
    const float* edge_aux = (const float*)d_in[3];
    const float* W_node   = (const float*)d_in[4];
    const float* b_node   = (const float*)d_in[5];
    const float* W_edge   = (const float*)d_in[6];
    const float* b_edge   = (const float*)d_in[7];
    float* out = (float*)d_out;

    node_kernel<<<NRES, 256>>>(X, C, node_aux, W_node, b_node, out);
    edge_kernel<<<NBLK, 256>>>(X, C, edge_aux, W_edge, b_edge, out);
}

// round 16
// speedup vs baseline: 1.3458x; 1.3458x over previous
#include <cuda_runtime.h>
#include <math.h>

#define NRES 768
#define DN   256
#define DE   128
#define EF   30
#define NT   24            // residue tiles (768/32)
#define TS   32            // tile size
#define NSUB 16            // sub-iterations per block (2 i-rows each)
#define NPAIRS 300         // NT*(NT+1)/2
#define RS   40            // sA row stride in words (conflict-free for uint2 frags)

// ---- output layout (floats), concatenation of the reference tuple ----
#define NODE_OFF 0ULL
#define EDGE_OFF (768ULL * 256ULL)                       // 196608
#define IDX_OFF  (EDGE_OFF + 768ULL * 768ULL * 128ULL)   // 75694080
#define MI_OFF   (IDX_OFF + 768ULL * 768ULL)             // 76283904
#define MIJ_OFF  (MI_OFF + 768ULL)                       // 76284672

// scratch: per-residue frames R (row-major 3x3)
__device__ float g_R[NRES * 9];

__device__ __forceinline__ float3 ld3(const float* p) { return make_float3(p[0], p[1], p[2]); }
__device__ __forceinline__ float3 vsub(float3 a, float3 b) { return make_float3(a.x - b.x, a.y - b.y, a.z - b.z); }
__device__ __forceinline__ float  vdot(float3 a, float3 b) { return a.x * b.x + a.y * b.y + a.z * b.z; }
__device__ __forceinline__ float3 vcross(float3 a, float3 b) {
    return make_float3(a.y * b.z - a.z * b.y, a.z * b.x - a.x * b.z, a.x * b.y - a.y * b.x);
}
__device__ __forceinline__ float  vnorm(float3 a) { return sqrtf(vdot(a, a) + 1e-8f); }
__device__ __forceinline__ float3 vunit(float3 a) { float r = 1.0f / vnorm(a); return make_float3(a.x * r, a.y * r, a.z * r); }

// tf32 round (rna) -> fp32 bit pattern with low mantissa cleared
__device__ __forceinline__ unsigned tf32r(float x) {
    unsigned r; asm("cvt.rna.tf32.f32 %0, %1;" : "=r"(r) : "f"(x)); return r;
}

// m16n8k8 tf32 MMA, D += A*B
__device__ __forceinline__ void mma_tf32(float d[4], const unsigned a[4], const unsigned b[2]) {
    asm volatile(
        "mma.sync.aligned.m16n8k8.row.col.f32.tf32.tf32.f32 "
        "{%0,%1,%2,%3}, {%4,%5,%6,%7}, {%8,%9}, {%0,%1,%2,%3};"
        : "+f"(d[0]), "+f"(d[1]), "+f"(d[2]), "+f"(d[3])
        : "r"(a[0]), "r"(a[1]), "r"(a[2]), "r"(a[3]), "r"(b[0]), "r"(b[1]));
}

// map MMA tile row e (0..127) of a sub to global (iG, jG)
__device__ __forceinline__ void rowmap(int e, int ItTS, int JtTS, int sub,
                                       int& iG, int& jG) {
    int f = e & 63;
    int il = f >> 5, jl = f & 31;
    if (e < 64) { iG = ItTS + sub * 2 + il; jG = JtTS + jl; }
    else        { iG = JtTS + jl;           jG = ItTS + sub * 2 + il; }
}

// ============================================================================
// idx/mask kernel: fully coalesced writes of edge_idx and mask_ij.
// grid = 2304 blocks x 256 threads, one (i,j) per thread.
// ============================================================================
__global__ void __launch_bounds__(256) idx_mask_kernel(
    const int* __restrict__ C, float* __restrict__ out)
{
    const int t = blockIdx.x * 256 + threadIdx.x;   // 0 .. 768*768-1
    const int i = t >> 9 << 0;                      // placeholder (recomputed below)
    const int ii = t / NRES, jj = t - ii * NRES;
    float mi = (C[ii] > 0) ? 1.0f : 0.0f;
    float mj = (C[jj] > 0) ? 1.0f : 0.0f;
    out[IDX_OFF + t] = (float)jj;
    out[MIJ_OFF + t] = mi * mj;
    (void)i;
}

// ============================================================================
// Node kernel (tiny)
// ============================================================================
__global__ void __launch_bounds__(256) node_kernel(
    const float* __restrict__ X, const int* __restrict__ C,
    const float* __restrict__ aux, const float* __restrict__ Wn,
    const float* __restrict__ bn, float* __restrict__ out)
{
    __shared__ float sfeat[7];
    __shared__ float smask;
    const int n = blockIdx.x;

    if (threadIdx.x == 0) {
        const float* xp = X + n * 12;
        float3 Na = ld3(xp), Ca = ld3(xp + 3), Cc = ld3(xp + 6), Ox = ld3(xp + 9);

        float d1 = logf(vnorm(vsub(Ca, Na)) + 0.001f);
        float d2 = logf(vnorm(vsub(Cc, Ca)) + 0.001f);
        float d3 = logf(vnorm(vsub(Ox, Cc)) + 0.001f);
        float a1 = vdot(vunit(vsub(Na, Ca)), vunit(vsub(Cc, Ca)));
        float a2 = vdot(vunit(vsub(Ca, Cc)), vunit(vsub(Ox, Cc)));

        float3 b0 = vsub(Ca, Na), b1 = vsub(Cc, Ca), b2 = vsub(Ox, Cc);
        float3 n1 = vcross(b0, b1), n2 = vcross(b1, b2);
        float3 ub1 = vunit(b1);
        float3 m1 = vcross(n1, ub1);
        float xx = vdot(n1, n2), yy = vdot(m1, n2);
        float r = sqrtf(xx * xx + yy * yy + 1e-8f);

        sfeat[0] = d1; sfeat[1] = d2; sfeat[2] = d3;
        sfeat[3] = a1; sfeat[4] = a2;
        sfeat[5] = yy / r; sfeat[6] = xx / r;

        float mi = (C[n] > 0) ? 1.0f : 0.0f;
        smask = mi;
        out[MI_OFF + n] = mi;

        float3 e1 = ub1;
        float3 v  = vunit(vsub(Na, Ca));
        float d  = vdot(v, e1);
        float3 w = make_float3(v.x - d * e1.x, v.y - d * e1.y, v.z - d * e1.z);
        float3 e2 = vunit(w);
        float3 e3 = vcross(e1, e2);
        float* rp = g_R + n * 9;
        rp[0] = e1.x; rp[1] = e1.y; rp[2] = e1.z;
        rp[3] = e2.x; rp[4] = e2.y; rp[5] = e2.z;
        rp[6] = e3.x; rp[7] = e3.y; rp[8] = e3.z;
    }
    __syncthreads();

    const int c = threadIdx.x;
    float acc = bn[c];
#pragma unroll
    for (int k = 0; k < 7; k++) acc = fmaf(sfeat[k], Wn[k * DN + c], acc);
    float mi = smask;
    out[NODE_OFF + (size_t)n * DN + c] = mi * (acc + aux[(size_t)n * DN + c]);
}

// A smem layout (fragment-native, tf32 hi only): row stride RS=40 words.
// word for feature k of row e: e*RS + (kt*4 + (k&3))*2 + ((k&7)>=4 ? 1 : 0)
__device__ __forceinline__ void astore(unsigned* sA, int e, int k, float v) {
    int idx = e * RS + (((k >> 3) << 2) + (k & 3)) * 2 + (((k & 7) >= 4) ? 1 : 0);
    sA[idx] = tf32r(v);
}

// ============================================================================
// Edge kernel (R13 champion structure): symmetric tile-pair blocks, 1xTF32
// MMA (weights in registers), fragment-native A tile (uint2 loads), hoisted
// epilogue loads. idx/mask_ij writes moved out to idx_mask_kernel.
// ============================================================================
__global__ void __launch_bounds__(256, 2) edge_kernel(
    const float* __restrict__ X, const int* __restrict__ C,
    const float* __restrict__ aux, const float* __restrict__ We,
    const float* __restrict__ be, float* __restrict__ out)
{
    __shared__ __align__(16) unsigned sA[128 * RS];   // 20 KB: 128 feature rows
    __shared__ float sXi[TS * 12], sXj[TS * 12];
    __shared__ float sRi[TS * 9],  sRj[TS * 9];
    __shared__ int   sCi[TS], sCj[TS];
    __shared__ float sb[DE];

    const int tid = threadIdx.x;
    const int lane = tid & 31, warp = tid >> 5;
    const int gid = lane >> 2, tg = lane & 3;
    const int wm = warp & 1;       // 2 m-blocks of 16 rows
    const int wn = warp >> 1;      // 4 n-blocks of 32 channels
    const int c0 = wn * 32 + tg * 8;

    // ---- triangular decode: blockIdx.x -> (It, Jt), It <= Jt ----
    int It = 0, rem = blockIdx.x, len = NT;
    while (rem >= len) { rem -= len; It++; len--; }
    const int Jt = It + rem;
    const bool isDiag = (It == Jt);
    const int ItTS = It * TS, JtTS = Jt * TS;

    // ---- B fragments (tf32 hi only) into registers ----
    unsigned Bh[4][4][2];
    {
        const int chan_base = wn * 32 + (gid >> 1) * 8 + (gid & 1);
#pragma unroll
        for (int kt = 0; kt < 4; kt++)
#pragma unroll
            for (int n = 0; n < 4; n++)
#pragma unroll
                for (int s = 0; s < 2; s++) {
                    int k = kt * 8 + tg + s * 4;
                    float w = (k < EF) ? We[k * DE + chan_base + n * 2] : 0.0f;
                    Bh[kt][n][s] = tf32r(w);
                }
    }

    // ---- stage tile data ----
    for (int t = tid; t < TS * 12; t += 256) {
        sXi[t] = X[ItTS * 12 + t];
        sXj[t] = X[JtTS * 12 + t];
    }
    for (int t = tid; t < TS * 9; t += 256) {
        sRi[t] = g_R[ItTS * 9 + t];
        sRj[t] = g_R[JtTS * 9 + t];
    }
    if (tid < TS) { sCi[tid] = C[ItTS + tid]; sCj[tid] = C[JtTS + tid]; }
    if (tid < DE) sb[tid] = be[tid];
    if (tid < 128) {  // zero pad words for k=30,31 (idx 29, 31; never rewritten)
        sA[tid * RS + 29] = 0u;
        sA[tid * RS + 31] = 0u;
    }
    __syncthreads();

    for (int sub = 0; sub < NSUB; sub++) {
        // ---- phase 1: 64 pairs (2 i-rows x 32 j), 4 threads/pair ----
        {
            const int p = tid >> 2, r = tid & 3;
            const int il = p >> 5, jl = p & 31;
            const int iL = sub * 2 + il;
            const int iG = ItTS + iL, jG = JtTS + jl;
            const int frow = il * 32 + jl, rrow = 64 + frow;

            // D: thread handles i-atom r vs all 4 j-atoms (shared both dirs)
            const float xpx = sXi[iL * 12 + r * 3 + 0];
            const float xpy = sXi[iL * 12 + r * 3 + 1];
            const float xpz = sXi[iL * 12 + r * 3 + 2];
#pragma unroll
            for (int q = 0; q < 4; q++) {
                float dx = xpx - sXj[jl * 12 + q * 3 + 0];
                float dy = xpy - sXj[jl * 12 + q * 3 + 1];
                float dz = xpz - sXj[jl * 12 + q * 3 + 2];
                float d2 = dx * dx + dy * dy + dz * dz + 1e-8f;
                float dist = d2 * rsqrtf(d2);
                float v = __logf(dist + 0.01f);
                astore(sA, frow, r * 4 + q, v);
                if (!isDiag) astore(sA, rrow, q * 4 + r, v);
            }

            if (r < 3) {
                // Rrel row r (rev = transpose, no recompute)
                const float a0 = sRi[iL * 9 + r * 3 + 0];
                const float a1 = sRi[iL * 9 + r * 3 + 1];
                const float a2 = sRi[iL * 9 + r * 3 + 2];
#pragma unroll
                for (int q = 0; q < 3; q++) {
                    float v = a0 * sRj[jl * 9 + q * 3 + 0]
                            + a1 * sRj[jl * 9 + q * 3 + 1]
                            + a2 * sRj[jl * 9 + q * 3 + 2];
                    astore(sA, frow, 16 + r * 3 + q, v);
                    if (!isDiag) astore(sA, rrow, 16 + q * 3 + r, v);
                }
            } else {
                // trel (shared norm: ||R dt|| = ||dt||), chain, sep
                float dtx = sXj[jl * 12 + 3] - sXi[iL * 12 + 3];
                float dty = sXj[jl * 12 + 4] - sXi[iL * 12 + 4];
                float dtz = sXj[jl * 12 + 5] - sXi[iL * 12 + 5];
                float rn = rsqrtf(dtx * dtx + dty * dty + dtz * dtz + 1e-8f);
#pragma unroll
                for (int q = 0; q < 3; q++) {
                    float tf = (sRi[iL * 9 + q * 3 + 0] * dtx
                              + sRi[iL * 9 + q * 3 + 1] * dty
                              + sRi[iL * 9 + q * 3 + 2] * dtz) * rn;
                    astore(sA, frow, 25 + q, tf);
                    if (!isDiag) {
                        float tr = -(sRj[jl * 9 + q * 3 + 0] * dtx
                                   + sRj[jl * 9 + q * 3 + 1] * dty
                                   + sRj[jl * 9 + q * 3 + 2] * dtz) * rn;
                        astore(sA, rrow, 25 + q, tr);
                    }
                }
                float sc = (sCi[iL] == sCj[jl]) ? 1.0f : 0.0f;
                astore(sA, frow, 28, sc);
                int dsep = jG - iG; dsep = min(32, max(-32, dsep));
                float sepv = (float)dsep * (1.0f / 32.0f);
                astore(sA, frow, 29, sepv);
                if (!isDiag) {
                    astore(sA, rrow, 28, sc);
                    astore(sA, rrow, 29, -sepv);
                }
            }
        }
        __syncthreads();

        // ---- phase 2: MMA + epilogue over row-groups of 32 ----
        const int ngroups = isDiag ? 2 : 4;
        for (int g = 0; g < ngroups; g++) {
            const int e0 = g * 32 + wm * 16 + gid;      // row 0
            const int el1 = e0 + 8;                     // row 1

            // analytic row -> (iG, jG, mij)
            int iG0, jG0, iG1, jG1;
            float mj0, mj1;
            {
                int f0 = e0 & 63, f1 = el1 & 63;
                int il0 = f0 >> 5, jl0 = f0 & 31;
                int il1 = f1 >> 5, jl1 = f1 & 31;
                mj0 = (sCi[sub * 2 + il0] > 0 && sCj[jl0] > 0) ? 1.0f : 0.0f;
                mj1 = (sCi[sub * 2 + il1] > 0 && sCj[jl1] > 0) ? 1.0f : 0.0f;
                rowmap(e0, ItTS, JtTS, sub, iG0, jG0);
                rowmap(el1, ItTS, JtTS, sub, iG1, jG1);
            }
            size_t base0 = ((size_t)iG0 * NRES + jG0) * DE + c0;
            size_t base1 = ((size_t)iG1 * NRES + jG1) * DE + c0;

            // hoisted aux loads (hidden under the MMA chain)
            float4 x0 = __ldcs((const float4*)&aux[base0]);
            float4 x1 = __ldcs((const float4*)&aux[base0 + 4]);
            float4 y0 = __ldcs((const float4*)&aux[base1]);
            float4 y1 = __ldcs((const float4*)&aux[base1 + 4]);

            float acc[4][4] = {};
#pragma unroll
            for (int kt = 0; kt < 4; kt++) {
                const unsigned* p0 = &sA[e0 * RS + (kt * 4 + tg) * 2];
                uint2 q0 = *(const uint2*)p0;             // row e0:  ah_k, ah_k+4
                uint2 q1 = *(const uint2*)(p0 + 8 * RS);  // row e0+8
                unsigned ah[4] = {q0.x, q1.x, q0.y, q1.y};
#pragma unroll
                for (int n = 0; n < 4; n++)
                    mma_tf32(acc[n], ah, Bh[kt][n]);
            }

            float4 bv0 = *(const float4*)&sb[c0];
            float4 bv1 = *(const float4*)&sb[c0 + 4];
            float4 o;
            o.x = mj0 * (acc[0][0] + bv0.x + x0.x);
            o.y = mj0 * (acc[0][1] + bv0.y + x0.y);
            o.z = mj0 * (acc[1][0] + bv0.z + x0.z);
            o.w = mj0 * (acc[1][1] + bv0.w + x0.w);
            __stcs((float4*)&out[EDGE_OFF + base0], o);
            o.x = mj0 * (acc[2][0] + bv1.x + x1.x);
            o.y = mj0 * (acc[2][1] + bv1.y + x1.y);
            o.z = mj0 * (acc[3][0] + bv1.z + x1.z);
            o.w = mj0 * (acc[3][1] + bv1.w + x1.w);
            __stcs((float4*)&out[EDGE_OFF + base0 + 4], o);
            o.x = mj1 * (acc[0][2] + bv0.x + y0.x);
            o.y = mj1 * (acc[0][3] + bv0.y + y0.y);
            o.z = mj1 * (acc[1][2] + bv0.z + y0.z);
            o.w = mj1 * (acc[1][3] + bv0.w + y0.w);
            __stcs((float4*)&out[EDGE_OFF + base1], o);
            o.x = mj1 * (acc[2][2] + bv1.x + y1.x);
            o.y = mj1 * (acc[2][3] + bv1.y + y1.y);
            o.z = mj1 * (acc[3][2] + bv1.z + y1.z);
            o.w = mj1 * (acc[3][3] + bv1.w + y1.w);
            __stcs((float4*)&out[EDGE_OFF + base1 + 4], o);
        }
        __syncthreads();   // protect sA before next sub's phase 1
    }
}

extern "C" void kernel_launch(void* const* d_in, const int* in_sizes, int n_in,
                              void* d_out, int out_size)
{
    const float* X        = (const float*)d_in[0];
    const int*   C        = (const int*)  d_in[1];
    const float* node_aux = (const float*)d_in[2];
    const float* edge_aux = (const float*)d_in[3];
    const float* W_node   = (const float*)d_in[4];
    const float* b_node   = (const float*)d_in[5];
    const float* W_edge   = (const float*)d_in[6];
    const float* b_edge   = (const float*)d_in[7];
    float* out = (float*)d_out;

    idx_mask_kernel<<<(NRES * NRES) / 256, 256>>>(C, out);
    node_kernel<<<NRES, 256>>>(X, C, node_aux, W_node, b_node, out);
    edge_kernel<<<NPAIRS, 256>>>(X, C, edge_aux, W_edge, b_edge, out);
}

// round 17
// speedup vs baseline: 1.3667x; 1.0156x over previous
#include <cuda_runtime.h>
#include <math.h>

#define NRES 768
#define DN   256
#define DE   128
#define EF   30
#define NT   24            // residue tiles (768/32)
#define TS   32            // tile size
#define NSUB 16            // sub-iterations per block (2 i-rows each)
#define NPAIRS 300         // NT*(NT+1)/2
#define RS   40            // sA row stride in words (conflict-free for uint2 frags)

// ---- output layout (floats), concatenation of the reference tuple ----
#define NODE_OFF 0ULL
#define EDGE_OFF (768ULL * 256ULL)                       // 196608
#define IDX_OFF  (EDGE_OFF + 768ULL * 768ULL * 128ULL)   // 75694080
#define MI_OFF   (IDX_OFF + 768ULL * 768ULL)             // 76283904
#define MIJ_OFF  (MI_OFF + 768ULL)                       // 76284672

// scratch: per-residue frames R (row-major 3x3)
__device__ float g_R[NRES * 9];

__device__ __forceinline__ float3 ld3(const float* p) { return make_float3(p[0], p[1], p[2]); }
__device__ __forceinline__ float3 vsub(float3 a, float3 b) { return make_float3(a.x - b.x, a.y - b.y, a.z - b.z); }
__device__ __forceinline__ float  vdot(float3 a, float3 b) { return a.x * b.x + a.y * b.y + a.z * b.z; }
__device__ __forceinline__ float3 vcross(float3 a, float3 b) {
    return make_float3(a.y * b.z - a.z * b.y, a.z * b.x - a.x * b.z, a.x * b.y - a.y * b.x);
}
__device__ __forceinline__ float  vnorm(float3 a) { return sqrtf(vdot(a, a) + 1e-8f); }
__device__ __forceinline__ float3 vunit(float3 a) { float r = 1.0f / vnorm(a); return make_float3(a.x * r, a.y * r, a.z * r); }

// tf32 round (rna) -> fp32 bit pattern with low mantissa cleared
__device__ __forceinline__ unsigned tf32r(float x) {
    unsigned r; asm("cvt.rna.tf32.f32 %0, %1;" : "=r"(r) : "f"(x)); return r;
}

// m16n8k8 tf32 MMA, D += A*B
__device__ __forceinline__ void mma_tf32(float d[4], const unsigned a[4], const unsigned b[2]) {
    asm volatile(
        "mma.sync.aligned.m16n8k8.row.col.f32.tf32.tf32.f32 "
        "{%0,%1,%2,%3}, {%4,%5,%6,%7}, {%8,%9}, {%0,%1,%2,%3};"
        : "+f"(d[0]), "+f"(d[1]), "+f"(d[2]), "+f"(d[3])
        : "r"(a[0]), "r"(a[1]), "r"(a[2]), "r"(a[3]), "r"(b[0]), "r"(b[1]));
}

// map MMA tile row e (0..127) of a sub to global (iG, jG)
__device__ __forceinline__ void rowmap(int e, int ItTS, int JtTS, int sub,
                                       int& iG, int& jG) {
    int f = e & 63;
    int il = f >> 5, jl = f & 31;
    if (e < 64) { iG = ItTS + sub * 2 + il; jG = JtTS + jl; }
    else        { iG = JtTS + jl;           jG = ItTS + sub * 2 + il; }
}

// ============================================================================
// Node kernel (tiny)
// ============================================================================
__global__ void __launch_bounds__(256) node_kernel(
    const float* __restrict__ X, const int* __restrict__ C,
    const float* __restrict__ aux, const float* __restrict__ Wn,
    const float* __restrict__ bn, float* __restrict__ out)
{
    __shared__ float sfeat[7];
    __shared__ float smask;
    const int n = blockIdx.x;

    if (threadIdx.x == 0) {
        const float* xp = X + n * 12;
        float3 Na = ld3(xp), Ca = ld3(xp + 3), Cc = ld3(xp + 6), Ox = ld3(xp + 9);

        float d1 = logf(vnorm(vsub(Ca, Na)) + 0.001f);
        float d2 = logf(vnorm(vsub(Cc, Ca)) + 0.001f);
        float d3 = logf(vnorm(vsub(Ox, Cc)) + 0.001f);
        float a1 = vdot(vunit(vsub(Na, Ca)), vunit(vsub(Cc, Ca)));
        float a2 = vdot(vunit(vsub(Ca, Cc)), vunit(vsub(Ox, Cc)));

        float3 b0 = vsub(Ca, Na), b1 = vsub(Cc, Ca), b2 = vsub(Ox, Cc);
        float3 n1 = vcross(b0, b1), n2 = vcross(b1, b2);
        float3 ub1 = vunit(b1);
        float3 m1 = vcross(n1, ub1);
        float xx = vdot(n1, n2), yy = vdot(m1, n2);
        float r = sqrtf(xx * xx + yy * yy + 1e-8f);

        sfeat[0] = d1; sfeat[1] = d2; sfeat[2] = d3;
        sfeat[3] = a1; sfeat[4] = a2;
        sfeat[5] = yy / r; sfeat[6] = xx / r;

        float mi = (C[n] > 0) ? 1.0f : 0.0f;
        smask = mi;
        out[MI_OFF + n] = mi;

        float3 e1 = ub1;
        float3 v  = vunit(vsub(Na, Ca));
        float d  = vdot(v, e1);
        float3 w = make_float3(v.x - d * e1.x, v.y - d * e1.y, v.z - d * e1.z);
        float3 e2 = vunit(w);
        float3 e3 = vcross(e1, e2);
        float* rp = g_R + n * 9;
        rp[0] = e1.x; rp[1] = e1.y; rp[2] = e1.z;
        rp[3] = e2.x; rp[4] = e2.y; rp[5] = e2.z;
        rp[6] = e3.x; rp[7] = e3.y; rp[8] = e3.z;
    }
    __syncthreads();

    const int c = threadIdx.x;
    float acc = bn[c];
#pragma unroll
    for (int k = 0; k < 7; k++) acc = fmaf(sfeat[k], Wn[k * DN + c], acc);
    float mi = smask;
    out[NODE_OFF + (size_t)n * DN + c] = mi * (acc + aux[(size_t)n * DN + c]);
}

// A smem layout (fragment-native, tf32 hi only): row stride RS=40 words.
// word for feature k of row e: e*RS + (kt*4 + (k&3))*2 + ((k&7)>=4 ? 1 : 0)
__device__ __forceinline__ void astore(unsigned* sA, int e, int k, float v) {
    int idx = e * RS + (((k >> 3) << 2) + (k & 3)) * 2 + (((k & 7) >= 4) ? 1 : 0);
    sA[idx] = tf32r(v);
}

// ============================================================================
// Edge kernel (champion structure): symmetric tile-pair blocks, 1xTF32 MMA
// (weights in registers), fragment-native A tile (uint2 loads), hoisted
// epilogue loads. idx/mask_ij written COALESCED once per block at staging.
// ============================================================================
__global__ void __launch_bounds__(256, 2) edge_kernel(
    const float* __restrict__ X, const int* __restrict__ C,
    const float* __restrict__ aux, const float* __restrict__ We,
    const float* __restrict__ be, float* __restrict__ out)
{
    __shared__ __align__(16) unsigned sA[128 * RS];   // 20 KB: 128 feature rows
    __shared__ float sXi[TS * 12], sXj[TS * 12];
    __shared__ float sRi[TS * 9],  sRj[TS * 9];
    __shared__ int   sCi[TS], sCj[TS];
    __shared__ float sb[DE];

    const int tid = threadIdx.x;
    const int lane = tid & 31, warp = tid >> 5;
    const int gid = lane >> 2, tg = lane & 3;
    const int wm = warp & 1;       // 2 m-blocks of 16 rows
    const int wn = warp >> 1;      // 4 n-blocks of 32 channels
    const int c0 = wn * 32 + tg * 8;

    // ---- triangular decode: blockIdx.x -> (It, Jt), It <= Jt ----
    int It = 0, rem = blockIdx.x, len = NT;
    while (rem >= len) { rem -= len; It++; len--; }
    const int Jt = It + rem;
    const bool isDiag = (It == Jt);
    const int ItTS = It * TS, JtTS = Jt * TS;

    // ---- B fragments (tf32 hi only) into registers ----
    unsigned Bh[4][4][2];
    {
        const int chan_base = wn * 32 + (gid >> 1) * 8 + (gid & 1);
#pragma unroll
        for (int kt = 0; kt < 4; kt++)
#pragma unroll
            for (int n = 0; n < 4; n++)
#pragma unroll
                for (int s = 0; s < 2; s++) {
                    int k = kt * 8 + tg + s * 4;
                    float w = (k < EF) ? We[k * DE + chan_base + n * 2] : 0.0f;
                    Bh[kt][n][s] = tf32r(w);
                }
    }

    // ---- stage tile data ----
    for (int t = tid; t < TS * 12; t += 256) {
        sXi[t] = X[ItTS * 12 + t];
        sXj[t] = X[JtTS * 12 + t];
    }
    for (int t = tid; t < TS * 9; t += 256) {
        sRi[t] = g_R[ItTS * 9 + t];
        sRj[t] = g_R[JtTS * 9 + t];
    }
    if (tid < TS) { sCi[tid] = C[ItTS + tid]; sCj[tid] = C[JtTS + tid]; }
    if (tid < DE) sb[tid] = be[tid];
    if (tid < 128) {  // zero pad words for k=30,31 (idx 29, 31; never rewritten)
        sA[tid * RS + 29] = 0u;
        sA[tid * RS + 31] = 0u;
    }
    __syncthreads();

    // ---- coalesced idx/mask_ij writes for this tile pair (once per block) ----
    {
        for (int rr = warp; rr < TS; rr += 8) {
            // forward region: row ItTS+rr, cols JtTS..JtTS+31
            float mif = (sCi[rr] > 0) ? 1.0f : 0.0f;
            float mjf = (sCj[lane] > 0) ? 1.0f : 0.0f;
            size_t f = (size_t)(ItTS + rr) * NRES + JtTS + lane;
            out[IDX_OFF + f] = (float)(JtTS + lane);
            out[MIJ_OFF + f] = mif * mjf;
            if (!isDiag) {
                // reverse region: row JtTS+rr, cols ItTS..ItTS+31
                float mir = (sCj[rr] > 0) ? 1.0f : 0.0f;
                float mjr = (sCi[lane] > 0) ? 1.0f : 0.0f;
                size_t rv = (size_t)(JtTS + rr) * NRES + ItTS + lane;
                out[IDX_OFF + rv] = (float)(ItTS + lane);
                out[MIJ_OFF + rv] = mir * mjr;
            }
        }
    }

    for (int sub = 0; sub < NSUB; sub++) {
        // ---- phase 1: 64 pairs (2 i-rows x 32 j), 4 threads/pair ----
        {
            const int p = tid >> 2, r = tid & 3;
            const int il = p >> 5, jl = p & 31;
            const int iL = sub * 2 + il;
            const int iG = ItTS + iL, jG = JtTS + jl;
            const int frow = il * 32 + jl, rrow = 64 + frow;

            // D: thread handles i-atom r vs all 4 j-atoms (shared both dirs)
            const float xpx = sXi[iL * 12 + r * 3 + 0];
            const float xpy = sXi[iL * 12 + r * 3 + 1];
            const float xpz = sXi[iL * 12 + r * 3 + 2];
#pragma unroll
            for (int q = 0; q < 4; q++) {
                float dx = xpx - sXj[jl * 12 + q * 3 + 0];
                float dy = xpy - sXj[jl * 12 + q * 3 + 1];
                float dz = xpz - sXj[jl * 12 + q * 3 + 2];
                float d2 = dx * dx + dy * dy + dz * dz + 1e-8f;
                float dist = d2 * rsqrtf(d2);
                float v = __logf(dist + 0.01f);
                astore(sA, frow, r * 4 + q, v);
                if (!isDiag) astore(sA, rrow, q * 4 + r, v);
            }

            if (r < 3) {
                // Rrel row r (rev = transpose, no recompute)
                const float a0 = sRi[iL * 9 + r * 3 + 0];
                const float a1 = sRi[iL * 9 + r * 3 + 1];
                const float a2 = sRi[iL * 9 + r * 3 + 2];
#pragma unroll
                for (int q = 0; q < 3; q++) {
                    float v = a0 * sRj[jl * 9 + q * 3 + 0]
                            + a1 * sRj[jl * 9 + q * 3 + 1]
                            + a2 * sRj[jl * 9 + q * 3 + 2];
                    astore(sA, frow, 16 + r * 3 + q, v);
                    if (!isDiag) astore(sA, rrow, 16 + q * 3 + r, v);
                }
            } else {
                // trel (shared norm: ||R dt|| = ||dt||), chain, sep
                float dtx = sXj[jl * 12 + 3] - sXi[iL * 12 + 3];
                float dty = sXj[jl * 12 + 4] - sXi[iL * 12 + 4];
                float dtz = sXj[jl * 12 + 5] - sXi[iL * 12 + 5];
                float rn = rsqrtf(dtx * dtx + dty * dty + dtz * dtz + 1e-8f);
#pragma unroll
                for (int q = 0; q < 3; q++) {
                    float tf = (sRi[iL * 9 + q * 3 + 0] * dtx
                              + sRi[iL * 9 + q * 3 + 1] * dty
                              + sRi[iL * 9 + q * 3 + 2] * dtz) * rn;
                    astore(sA, frow, 25 + q, tf);
                    if (!isDiag) {
                        float tr = -(sRj[jl * 9 + q * 3 + 0] * dtx
                                   + sRj[jl * 9 + q * 3 + 1] * dty
                                   + sRj[jl * 9 + q * 3 + 2] * dtz) * rn;
                        astore(sA, rrow, 25 + q, tr);
                    }
                }
                float sc = (sCi[iL] == sCj[jl]) ? 1.0f : 0.0f;
                astore(sA, frow, 28, sc);
                int dsep = jG - iG; dsep = min(32, max(-32, dsep));
                float sepv = (float)dsep * (1.0f / 32.0f);
                astore(sA, frow, 29, sepv);
                if (!isDiag) {
                    astore(sA, rrow, 28, sc);
                    astore(sA, rrow, 29, -sepv);
                }
            }
        }
        __syncthreads();

        // ---- phase 2: MMA + epilogue over row-groups of 32 ----
        const int ngroups = isDiag ? 2 : 4;
        for (int g = 0; g < ngroups; g++) {
            const int e0 = g * 32 + wm * 16 + gid;      // row 0
            const int el1 = e0 + 8;                     // row 1

            // analytic row -> (iG, jG, mij)
            int iG0, jG0, iG1, jG1;
            float mj0, mj1;
            {
                int f0 = e0 & 63, f1 = el1 & 63;
                int il0 = f0 >> 5, jl0 = f0 & 31;
                int il1 = f1 >> 5, jl1 = f1 & 31;
                mj0 = (sCi[sub * 2 + il0] > 0 && sCj[jl0] > 0) ? 1.0f : 0.0f;
                mj1 = (sCi[sub * 2 + il1] > 0 && sCj[jl1] > 0) ? 1.0f : 0.0f;
                rowmap(e0, ItTS, JtTS, sub, iG0, jG0);
                rowmap(el1, ItTS, JtTS, sub, iG1, jG1);
            }
            size_t base0 = ((size_t)iG0 * NRES + jG0) * DE + c0;
            size_t base1 = ((size_t)iG1 * NRES + jG1) * DE + c0;

            // hoisted aux loads (hidden under the MMA chain)
            float4 x0 = __ldcs((const float4*)&aux[base0]);
            float4 x1 = __ldcs((const float4*)&aux[base0 + 4]);
            float4 y0 = __ldcs((const float4*)&aux[base1]);
            float4 y1 = __ldcs((const float4*)&aux[base1 + 4]);

            float acc[4][4] = {};
#pragma unroll
            for (int kt = 0; kt < 4; kt++) {
                const unsigned* p0 = &sA[e0 * RS + (kt * 4 + tg) * 2];
                uint2 q0 = *(const uint2*)p0;             // row e0:  ah_k, ah_k+4
                uint2 q1 = *(const uint2*)(p0 + 8 * RS);  // row e0+8
                unsigned ah[4] = {q0.x, q1.x, q0.y, q1.y};
#pragma unroll
                for (int n = 0; n < 4; n++)
                    mma_tf32(acc[n], ah, Bh[kt][n]);
            }

            float4 bv0 = *(const float4*)&sb[c0];
            float4 bv1 = *(const float4*)&sb[c0 + 4];
            float4 o;
            o.x = mj0 * (acc[0][0] + bv0.x + x0.x);
            o.y = mj0 * (acc[0][1] + bv0.y + x0.y);
            o.z = mj0 * (acc[1][0] + bv0.z + x0.z);
            o.w = mj0 * (acc[1][1] + bv0.w + x0.w);
            __stcs((float4*)&out[EDGE_OFF + base0], o);
            o.x = mj0 * (acc[2][0] + bv1.x + x1.x);
            o.y = mj0 * (acc[2][1] + bv1.y + x1.y);
            o.z = mj0 * (acc[3][0] + bv1.z + x1.z);
            o.w = mj0 * (acc[3][1] + bv1.w + x1.w);
            __stcs((float4*)&out[EDGE_OFF + base0 + 4], o);
            o.x = mj1 * (acc[0][2] + bv0.x + y0.x);
            o.y = mj1 * (acc[0][3] + bv0.y + y0.y);
            o.z = mj1 * (acc[1][2] + bv0.z + y0.z);
            o.w = mj1 * (acc[1][3] + bv0.w + y0.w);
            __stcs((float4*)&out[EDGE_OFF + base1], o);
            o.x = mj1 * (acc[2][2] + bv1.x + y1.x);
            o.y = mj1 * (acc[2][3] + bv1.y + y1.y);
            o.z = mj1 * (acc[3][2] + bv1.z + y1.z);
            o.w = mj1 * (acc[3][3] + bv1.w + y1.w);
            __stcs((float4*)&out[EDGE_OFF + base1 + 4], o);
        }
        __syncthreads();   // protect sA before next sub's phase 1
    }
}

extern "C" void kernel_launch(void* const* d_in, const int* in_sizes, int n_in,
                              void* d_out, int out_size)
{
    const float* X        = (const float*)d_in[0];
    const int*   C        = (const int*)  d_in[1];
    const float* node_aux = (const float*)d_in[2];
    const float* edge_aux = (const float*)d_in[3];
    const float* W_node   = (const float*)d_in[4];
    const float* b_node   = (const float*)d_in[5];
    const float* W_edge   = (const float*)d_in[6];
    const float* b_edge   = (const float*)d_in[7];
    float* out = (float*)d_out;

    node_kernel<<<NRES, 256>>>(X, C, node_aux, W_node, b_node, out);
    edge_kernel<<<NPAIRS, 256>>>(X, C, edge_aux, W_edge, b_edge, out);
}